// round 9
// baseline (speedup 1.0000x reference)
#include <cuda_runtime.h>
#include <cuda_bf16.h>
#include <cstdint>
#include <math.h>

// ---------------------------------------------------------------------------
// CustomLSTM: 2-layer LSTM, B=128, T=256, F=H=1024.
// Round 5:
//   * Same math as R1 (split-bf16 3-term GEMMs, hoisted input projection).
//   * The 1024-launch scan is now ONE persistent kernel (128 CTAs, software
//     grid barrier) -> 6 graph nodes total. Fixes the 2 MiB graph-upload
//     leak rule violation and removes all per-step launch overhead; step
//     weights (72 MB) stay L2-resident across all 256 steps.
// ---------------------------------------------------------------------------

#define DI __device__ __forceinline__

constexpr int BATCH = 128;
constexpr int SEQ   = 256;
constexpr int FDIM  = 1024;
constexpr int HDIM  = 1024;
constexpr int G4    = 4096;          // 4*H
constexpr int KSPL  = 3 * 1024;      // split-K (hi|hi|lo vs hi|lo|hi)
constexpr int MTOT  = BATCH * SEQ;   // 32768
constexpr int NCTA  = 128;           // persistent scan CTAs (all co-resident)

// ------------------------- device scratch (globals) ------------------------
__device__ __nv_bfloat16 g_Wih0s[(size_t)G4 * KSPL];
__device__ __nv_bfloat16 g_Whh0s[(size_t)G4 * KSPL];
__device__ __nv_bfloat16 g_Wih1s[(size_t)G4 * KSPL];
__device__ __nv_bfloat16 g_Whh1s[(size_t)G4 * KSPL];
__device__ __nv_bfloat16 g_xs[(size_t)MTOT * KSPL];           // split x
__device__ float         g_gates_x[(size_t)SEQ * BATCH * G4]; // [t][b][4H] (incl. bias0)
__device__ float         g_gates0[(size_t)BATCH * G4];        // layer0 preact
__device__ float         g_gates1[(size_t)BATCH * G4];        // layer1 preact
__device__ __nv_bfloat16 g_h0s[BATCH * KSPL];
__device__ __nv_bfloat16 g_h1s[BATCH * KSPL];
__device__ float         g_c0[BATCH * HDIM];
__device__ float         g_c1[BATCH * HDIM];
__device__ float         g_bias0[G4];
__device__ float         g_bias1[G4];

// software grid barrier state (self-resetting; gen is monotonic across replays)
__device__ unsigned g_bar_cnt;
__device__ unsigned g_bar_gen;

// ------------------------------ small helpers ------------------------------
DI float sigf(float x) { return 1.0f / (1.0f + __expf(-x)); }

DI void ldsm4(uint32_t* r, const __nv_bfloat16* p) {
    uint32_t a = (uint32_t)__cvta_generic_to_shared(p);
    asm volatile("ldmatrix.sync.aligned.m8n8.x4.shared.b16 {%0,%1,%2,%3}, [%4];"
                 : "=r"(r[0]), "=r"(r[1]), "=r"(r[2]), "=r"(r[3]) : "r"(a));
}

DI void mma16816(float* d, const uint32_t* a, uint32_t b0, uint32_t b1) {
    asm volatile(
        "mma.sync.aligned.m16n8k16.row.col.f32.bf16.bf16.f32 "
        "{%0,%1,%2,%3}, {%4,%5,%6,%7}, {%8,%9}, {%0,%1,%2,%3};"
        : "+f"(d[0]), "+f"(d[1]), "+f"(d[2]), "+f"(d[3])
        : "r"(a[0]), "r"(a[1]), "r"(a[2]), "r"(a[3]), "r"(b0), "r"(b1));
}

// sense-reversing grid barrier across NCTA co-resident CTAs
DI void grid_bar() {
    __syncthreads();
    if (threadIdx.x == 0) {
        unsigned gen = *(volatile unsigned*)&g_bar_gen;
        __threadfence();                       // release my phase's writes
        if (atomicAdd(&g_bar_cnt, 1u) == NCTA - 1u) {
            atomicExch(&g_bar_cnt, 0u);
            __threadfence();
            atomicExch(&g_bar_gen, gen + 1u);  // release
        } else {
            while (*(volatile unsigned*)&g_bar_gen == gen) { __nanosleep(32); }
        }
        __threadfence();                       // acquire other CTAs' writes
    }
    __syncthreads();
}

// --------------------------- prep / split kernels ---------------------------
__global__ void k_split_w(const float* __restrict__ W0, const float* __restrict__ W1,
                          const float* __restrict__ W2, const float* __restrict__ W3) {
    size_t idx = (size_t)blockIdx.x * blockDim.x + threadIdx.x;
    if (idx >= (size_t)4 * G4 * FDIM) return;
    int which = (int)(idx >> 22);
    int r = (int)(idx & 4194303);
    const float* W = which == 0 ? W0 : which == 1 ? W1 : which == 2 ? W2 : W3;
    __nv_bfloat16* Ws = which == 0 ? g_Wih0s : which == 1 ? g_Whh0s
                       : which == 2 ? g_Wih1s : g_Whh1s;
    int n = r >> 10, k = r & 1023;
    float v = W[r];
    __nv_bfloat16 hi = __float2bfloat16(v);
    __nv_bfloat16 lo = __float2bfloat16(v - __bfloat162float(hi));
    __nv_bfloat16* row = Ws + (size_t)n * KSPL;
    row[k] = hi; row[1024 + k] = lo; row[2048 + k] = hi;   // [Bh | Bl | Bh]
}

__global__ void k_split_x(const float* __restrict__ x) {
    size_t idx = (size_t)blockIdx.x * blockDim.x + threadIdx.x;
    if (idx >= (size_t)MTOT * FDIM) return;
    int m = (int)(idx >> 10), k = (int)(idx & 1023);
    float v = x[idx];
    __nv_bfloat16 hi = __float2bfloat16(v);
    __nv_bfloat16 lo = __float2bfloat16(v - __bfloat162float(hi));
    __nv_bfloat16* row = g_xs + (size_t)m * KSPL;
    row[k] = hi; row[1024 + k] = hi; row[2048 + k] = lo;   // [Ah | Ah | Al]
}

__global__ void k_bias(const float* b_ih0, const float* b_hh0,
                       const float* b_ih1, const float* b_hh1) {
    int i = blockIdx.x * blockDim.x + threadIdx.x;
    if (i < G4) {
        g_bias0[i] = b_ih0[i] + b_hh0[i];
        g_bias1[i] = b_ih1[i] + b_hh1[i];
    }
}

__global__ void k_init() {
    int i = blockIdx.x * blockDim.x + threadIdx.x;
    __nv_bfloat16 z = __float2bfloat16(0.0f);
    if (i < BATCH * KSPL) { g_h0s[i] = z; g_h1s[i] = z; }
    if (i < BATCH * HDIM) { g_c0[i] = 0.0f; g_c1[i] = 0.0f; }
}

// ------------------------------ GEMM mainloop -------------------------------
// C[BM,BN] += A[BM,KSPL] * B[BN,KSPL]^T, A/B row-major bf16, fp32 accum.
// Smem rows padded to 40 bf16 (conflict-free ldmatrix).
template <int BM, int BN, int WR, int WC, int NTH>
DI void gemm_acc(const __nv_bfloat16* __restrict__ Ab,
                 const __nv_bfloat16* __restrict__ Bm,
                 float* acc, __nv_bfloat16* sA, __nv_bfloat16* sB) {
    constexpr int WTM = BM / WR, WTN = BN / WC;
    constexpr int MT = WTM / 16, NG = WTN / 16;
    constexpr int AV = BM * 4 / NTH, BV = BN * 4 / NTH;
    const int tid = threadIdx.x;
    const int warp = tid >> 5, lane = tid & 31;
    const int wm = warp % WR, wn = warp / WR;
    const int lr = lane & 15, lc = (lane >> 4) << 3;

    uint4 pa[AV], pb[BV];
#pragma unroll
    for (int i = 0; i < AV; i++) {
        int v = tid + i * NTH;
        pa[i] = *reinterpret_cast<const uint4*>(Ab + (size_t)(v >> 2) * KSPL + ((v & 3) << 3));
    }
#pragma unroll
    for (int i = 0; i < BV; i++) {
        int v = tid + i * NTH;
        pb[i] = *reinterpret_cast<const uint4*>(Bm + (size_t)(v >> 2) * KSPL + ((v & 3) << 3));
    }

    for (int k0 = 0; k0 < KSPL; k0 += 32) {
#pragma unroll
        for (int i = 0; i < AV; i++) {
            int v = tid + i * NTH;
            *reinterpret_cast<uint4*>(sA + (v >> 2) * 40 + ((v & 3) << 3)) = pa[i];
        }
#pragma unroll
        for (int i = 0; i < BV; i++) {
            int v = tid + i * NTH;
            *reinterpret_cast<uint4*>(sB + (v >> 2) * 40 + ((v & 3) << 3)) = pb[i];
        }
        __syncthreads();
        if (k0 + 32 < KSPL) {
#pragma unroll
            for (int i = 0; i < AV; i++) {
                int v = tid + i * NTH;
                pa[i] = *reinterpret_cast<const uint4*>(
                    Ab + (size_t)(v >> 2) * KSPL + (k0 + 32) + ((v & 3) << 3));
            }
#pragma unroll
            for (int i = 0; i < BV; i++) {
                int v = tid + i * NTH;
                pb[i] = *reinterpret_cast<const uint4*>(
                    Bm + (size_t)(v >> 2) * KSPL + (k0 + 32) + ((v & 3) << 3));
            }
        }
#pragma unroll
        for (int kk = 0; kk < 32; kk += 16) {
            uint32_t ra[MT][4], rb[NG][4];
#pragma unroll
            for (int mi = 0; mi < MT; mi++)
                ldsm4(ra[mi], sA + (wm * WTM + mi * 16 + lr) * 40 + kk + lc);
#pragma unroll
            for (int ng = 0; ng < NG; ng++)
                ldsm4(rb[ng], sB + (wn * WTN + ng * 16 + lr) * 40 + kk + lc);
#pragma unroll
            for (int mi = 0; mi < MT; mi++)
#pragma unroll
                for (int ng = 0; ng < NG; ng++) {
                    mma16816(acc + ((mi * 2 * NG) + 2 * ng) * 4,     ra[mi], rb[ng][0], rb[ng][2]);
                    mma16816(acc + ((mi * 2 * NG) + 2 * ng + 1) * 4, ra[mi], rb[ng][1], rb[ng][3]);
                }
        }
        __syncthreads();
    }
}

// --------------------------- precompute big GEMM ----------------------------
// gates_x[t][b][:] = x[b][t] @ Wih0^T + (b_ih0 + b_hh0)
__global__ void __launch_bounds__(256) k_gemm_pre() {
    __shared__ __nv_bfloat16 sA[128 * 40];
    __shared__ __nv_bfloat16 sB[128 * 40];
    const int m0 = blockIdx.y * 128, n0 = blockIdx.x * 128;
    float acc[2 * 8 * 4];
#pragma unroll
    for (int i = 0; i < 64; i++) acc[i] = 0.0f;

    gemm_acc<128, 128, 4, 2, 256>(g_xs + (size_t)m0 * KSPL,
                                  g_Wih0s + (size_t)n0 * KSPL, acc, sA, sB);

    const int lane = threadIdx.x & 31, warp = threadIdx.x >> 5;
    const int wm = warp % 4, wn = warp / 4;
#pragma unroll
    for (int mi = 0; mi < 2; mi++)
#pragma unroll
        for (int nt = 0; nt < 8; nt++) {
            float* a4 = acc + ((mi * 8) + nt) * 4;
            int r = m0 + wm * 32 + mi * 16 + (lane >> 2);
            int c = n0 + wn * 64 + nt * 8 + ((lane & 3) << 1);
            {
                int b = r >> 8, t = r & 255;
                size_t d = (size_t)(t * BATCH + b) * G4 + c;
                g_gates_x[d]     = a4[0] + g_bias0[c];
                g_gates_x[d + 1] = a4[1] + g_bias0[c + 1];
            }
            {
                int r2 = r + 8;
                int b = r2 >> 8, t = r2 & 255;
                size_t d = (size_t)(t * BATCH + b) * G4 + c;
                g_gates_x[d]     = a4[2] + g_bias0[c];
                g_gates_x[d + 1] = a4[3] + g_bias0[c + 1];
            }
        }
}

// ----------------------- persistent scan (1 kernel) -------------------------
// 128 CTAs x 256 threads. Per step: A(gemm0) |bar| B(cell0) |bar| C(gemm1x2)
// |bar| D(cell1) -> next A (D and A(t+1) touch disjoint state; no bar needed).
// Epilogue mapping for gemm_acc<64,64,2,4,256>: WTM=32, WTN=16, MT=2, NG=1.
DI void epi64(const float* acc, int m0, int n0,
              float* __restrict__ dst, const float* __restrict__ add) {
    const int lane = threadIdx.x & 31, warp = threadIdx.x >> 5;
    const int wm = warp & 1, wn = warp >> 1;
#pragma unroll
    for (int mi = 0; mi < 2; mi++)
#pragma unroll
        for (int half = 0; half < 2; half++) {
            const float* a4 = acc + (mi * 2 + half) * 4;
            int r = m0 + wm * 32 + mi * 16 + (lane >> 2);
            int c = n0 + wn * 16 + half * 8 + ((lane & 3) << 1);
            size_t d = (size_t)r * G4 + c;
            dst[d]     = a4[0] + add[d];
            dst[d + 1] = a4[1] + add[d + 1];
            size_t d2 = d + (size_t)8 * G4;
            dst[d2]     = a4[2] + add[d2];
            dst[d2 + 1] = a4[3] + add[d2 + 1];
        }
}

DI void epi64_bias(const float* acc, int m0, int n0,
                   float* __restrict__ dst, const float* __restrict__ bias) {
    const int lane = threadIdx.x & 31, warp = threadIdx.x >> 5;
    const int wm = warp & 1, wn = warp >> 1;
#pragma unroll
    for (int mi = 0; mi < 2; mi++)
#pragma unroll
        for (int half = 0; half < 2; half++) {
            const float* a4 = acc + (mi * 2 + half) * 4;
            int r = m0 + wm * 32 + mi * 16 + (lane >> 2);
            int c = n0 + wn * 16 + half * 8 + ((lane & 3) << 1);
            size_t d = (size_t)r * G4 + c;
            dst[d]     = a4[0] + bias[c];
            dst[d + 1] = a4[1] + bias[c + 1];
            size_t d2 = d + (size_t)8 * G4;
            dst[d2]     = a4[2] + bias[c];
            dst[d2 + 1] = a4[3] + bias[c + 1];
        }
}

DI void cell_phase(int t, int layer, float* __restrict__ out) {
    int base = blockIdx.x * blockDim.x + threadIdx.x;     // 0..32767
    const float* g = layer ? g_gates1 : g_gates0;
    float* c = layer ? g_c1 : g_c0;
    __nv_bfloat16* hs = layer ? g_h1s : g_h0s;
#pragma unroll
    for (int e = 0; e < 4; e++) {
        int idx = base + e * (NCTA * 256);                // 131072 total
        int b = idx >> 10, j = idx & 1023;
        const float* gb = g + (size_t)b * G4;
        float iv = sigf(gb[j]);
        float fv = sigf(gb[1024 + j]);
        float gv = tanhf(gb[2048 + j]);
        float ov = sigf(gb[3072 + j]);
        float cn = fv * c[idx] + iv * gv;
        c[idx] = cn;
        float h = ov * tanhf(cn);
        __nv_bfloat16 hi = __float2bfloat16(h);
        float lo = h - __bfloat162float(hi);
        __nv_bfloat16* row = hs + (size_t)b * KSPL;
        row[j] = hi; row[1024 + j] = hi; row[2048 + j] = __float2bfloat16(lo);
        if (layer) out[(size_t)b * SEQ * HDIM + (size_t)t * HDIM + j] = h;
    }
}

__global__ void __launch_bounds__(256) k_scan(float* __restrict__ out) {
    __shared__ __nv_bfloat16 sA[64 * 40];
    __shared__ __nv_bfloat16 sB[64 * 40];
    const int m0 = (blockIdx.x & 1) * 64;       // 2 row tiles of M=128
    const int n0 = (blockIdx.x >> 1) * 64;      // 64 col tiles of N=4096

    for (int t = 0; t < SEQ; t++) {
        // --- A: gates0 = h0 @ Whh0^T + gates_x[t] ---
        {
            float acc[16];
#pragma unroll
            for (int i = 0; i < 16; i++) acc[i] = 0.0f;
            gemm_acc<64, 64, 2, 4, 256>(g_h0s + (size_t)m0 * KSPL,
                                        g_Whh0s + (size_t)n0 * KSPL, acc, sA, sB);
            epi64(acc, m0, n0, g_gates0, g_gates_x + (size_t)t * BATCH * G4);
        }
        grid_bar();
        // --- B: cell0 -> c0, h0s ---
        cell_phase(t, 0, out);
        grid_bar();
        // --- C: gates1 = h0 @ Wih1^T + h1 @ Whh1^T + bias1 ---
        {
            float acc[16];
#pragma unroll
            for (int i = 0; i < 16; i++) acc[i] = 0.0f;
            gemm_acc<64, 64, 2, 4, 256>(g_h0s + (size_t)m0 * KSPL,
                                        g_Wih1s + (size_t)n0 * KSPL, acc, sA, sB);
            gemm_acc<64, 64, 2, 4, 256>(g_h1s + (size_t)m0 * KSPL,
                                        g_Whh1s + (size_t)n0 * KSPL, acc, sA, sB);
            epi64_bias(acc, m0, n0, g_gates1, g_bias1);
        }
        grid_bar();
        // --- D: cell1 -> c1, h1s, out[:, t, :] ---
        cell_phase(t, 1, out);
        // no barrier: D touches {gates1(r), h1s/c1/out(w)}; next A touches
        // {h0s/Whh0s/gates_x(r), gates0(w)} — disjoint. All other pairs are
        // separated by >=1 barrier in the following iteration.
    }
}

// -------------------------------- launcher ----------------------------------
extern "C" void kernel_launch(void* const* d_in, const int* in_sizes, int n_in,
                              void* d_out, int out_size) {
    const float* x     = (const float*)d_in[0];
    const float* W_ih0 = (const float*)d_in[1];
    const float* b_ih0 = (const float*)d_in[2];
    const float* W_hh0 = (const float*)d_in[3];
    const float* b_hh0 = (const float*)d_in[4];
    const float* W_ih1 = (const float*)d_in[5];
    const float* b_ih1 = (const float*)d_in[6];
    const float* W_hh1 = (const float*)d_in[7];
    const float* b_hh1 = (const float*)d_in[8];
    float* out = (float*)d_out;

    // prep (4 nodes)
    k_split_w<<<(4 * G4 * FDIM + 255) / 256, 256>>>(W_ih0, W_hh0, W_ih1, W_hh1);
    k_bias<<<(G4 + 255) / 256, 256>>>(b_ih0, b_hh0, b_ih1, b_hh1);
    k_split_x<<<(MTOT * FDIM + 255) / 256, 256>>>(x);
    k_init<<<(BATCH * KSPL + 255) / 256, 256>>>();

    // big input-projection GEMM (all timesteps) (1 node)
    k_gemm_pre<<<dim3(G4 / 128, MTOT / 128), 256>>>();

    // persistent sequential scan (1 node)
    k_scan<<<NCTA, 256>>>(out);
}

// round 10
// speedup vs baseline: 1.8426x; 1.8426x over previous
#include <cuda_runtime.h>
#include <cuda_bf16.h>
#include <cstdint>
#include <math.h>

// ---------------------------------------------------------------------------
// CustomLSTM: 2-layer LSTM, B=128, T=256, F=H=1024.
// Round 9:
//   * split-bf16 3-term GEMMs (K=3072), hoisted input projection (unchanged).
//   * gate-interleaved weight permutation: each 64-col GEMM tile = [i|f|g|o]x16
//     h-columns -> LSTM cell fused into the GEMM epilogue (in-CTA, smem).
//     Cell state c lives in smem for the whole scan. Gates never touch gmem.
//   * h double-buffered by timestep parity -> ONE grid barrier per step.
//   * 4-stage cp.async pipeline in all GEMM mainloops (hides L2 latency).
// ---------------------------------------------------------------------------

#define DI __device__ __forceinline__

constexpr int BATCH = 128;
constexpr int SEQ   = 256;
constexpr int FDIM  = 1024;
constexpr int HDIM  = 1024;
constexpr int G4    = 4096;          // 4*H
constexpr int KSPL  = 3 * 1024;      // split-K (hi|hi|lo vs hi|lo|hi)
constexpr int MTOT  = BATCH * SEQ;   // 32768
constexpr int NCTA  = 128;           // persistent scan CTAs (all co-resident)

// ------------------------- device scratch (globals) ------------------------
__device__ __nv_bfloat16 g_Wih0s[(size_t)G4 * KSPL];
__device__ __nv_bfloat16 g_Whh0s[(size_t)G4 * KSPL];
__device__ __nv_bfloat16 g_Wih1s[(size_t)G4 * KSPL];
__device__ __nv_bfloat16 g_Whh1s[(size_t)G4 * KSPL];
__device__ __nv_bfloat16 g_xs[(size_t)MTOT * KSPL];           // split x
__device__ float         g_gates_x[(size_t)SEQ * BATCH * G4]; // [t][b][c] permuted cols
__device__ __nv_bfloat16 g_h0s[2][(size_t)BATCH * KSPL];      // double-buffered
__device__ __nv_bfloat16 g_h1s[2][(size_t)BATCH * KSPL];
__device__ float         g_bias0[G4];   // permuted
__device__ float         g_bias1[G4];   // permuted

// software grid barrier (gen monotonic across replays; cnt self-resets)
__device__ unsigned g_bar_cnt;
__device__ unsigned g_bar_gen;

// ------------------------------ small helpers ------------------------------
DI float sigf(float x) { return 1.0f / (1.0f + __expf(-x)); }

// gate-interleave permutation: orig row n = gate*1024 + j  ->
// col c = (j/16)*64 + gate*16 + (j%16). Tile n0 (64-aligned) covers
// j in [n0/4, n0/4+16), all 4 gates.
DI int gate_perm(int n) {
    int g = n >> 10, j = n & 1023;
    return ((j >> 4) << 6) + (g << 4) + (j & 15);
}

DI void ldsm4(uint32_t* r, const __nv_bfloat16* p) {
    uint32_t a = (uint32_t)__cvta_generic_to_shared(p);
    asm volatile("ldmatrix.sync.aligned.m8n8.x4.shared.b16 {%0,%1,%2,%3}, [%4];"
                 : "=r"(r[0]), "=r"(r[1]), "=r"(r[2]), "=r"(r[3]) : "r"(a));
}

DI void mma16816(float* d, const uint32_t* a, uint32_t b0, uint32_t b1) {
    asm volatile(
        "mma.sync.aligned.m16n8k16.row.col.f32.bf16.bf16.f32 "
        "{%0,%1,%2,%3}, {%4,%5,%6,%7}, {%8,%9}, {%0,%1,%2,%3};"
        : "+f"(d[0]), "+f"(d[1]), "+f"(d[2]), "+f"(d[3])
        : "r"(a[0]), "r"(a[1]), "r"(a[2]), "r"(a[3]), "r"(b0), "r"(b1));
}

DI void cp16(void* dst, const void* src) {
    uint32_t d = (uint32_t)__cvta_generic_to_shared(dst);
    asm volatile("cp.async.cg.shared.global [%0], [%1], 16;\n" :: "r"(d), "l"(src));
}
DI void cp_commit() { asm volatile("cp.async.commit_group;\n" ::: "memory"); }
DI void cp_wait2()  { asm volatile("cp.async.wait_group 2;\n"  ::: "memory"); }

DI void grid_bar() {
    __syncthreads();
    if (threadIdx.x == 0) {
        unsigned gen = *(volatile unsigned*)&g_bar_gen;
        __threadfence();
        if (atomicAdd(&g_bar_cnt, 1u) == NCTA - 1u) {
            atomicExch(&g_bar_cnt, 0u);
            __threadfence();
            atomicExch(&g_bar_gen, gen + 1u);
        } else {
            while (*(volatile unsigned*)&g_bar_gen == gen) { __nanosleep(32); }
        }
        __threadfence();
    }
    __syncthreads();
}

// --------------------------- prep / split kernels ---------------------------
__global__ void k_split_w(const float* __restrict__ W0, const float* __restrict__ W1,
                          const float* __restrict__ W2, const float* __restrict__ W3) {
    size_t idx = (size_t)blockIdx.x * blockDim.x + threadIdx.x;
    if (idx >= (size_t)4 * G4 * FDIM) return;
    int which = (int)(idx >> 22);
    int r = (int)(idx & 4194303);
    const float* W = which == 0 ? W0 : which == 1 ? W1 : which == 2 ? W2 : W3;
    __nv_bfloat16* Ws = which == 0 ? g_Wih0s : which == 1 ? g_Whh0s
                       : which == 2 ? g_Wih1s : g_Whh1s;
    int n = r >> 10, k = r & 1023;
    int c = gate_perm(n);
    float v = W[r];
    __nv_bfloat16 hi = __float2bfloat16(v);
    __nv_bfloat16 lo = __float2bfloat16(v - __bfloat162float(hi));
    __nv_bfloat16* row = Ws + (size_t)c * KSPL;
    row[k] = hi; row[1024 + k] = lo; row[2048 + k] = hi;   // [Bh | Bl | Bh]
}

__global__ void k_split_x(const float* __restrict__ x) {
    size_t idx = (size_t)blockIdx.x * blockDim.x + threadIdx.x;
    if (idx >= (size_t)MTOT * FDIM) return;
    int m = (int)(idx >> 10), k = (int)(idx & 1023);
    float v = x[idx];
    __nv_bfloat16 hi = __float2bfloat16(v);
    __nv_bfloat16 lo = __float2bfloat16(v - __bfloat162float(hi));
    __nv_bfloat16* row = g_xs + (size_t)m * KSPL;
    row[k] = hi; row[1024 + k] = hi; row[2048 + k] = lo;   // [Ah | Ah | Al]
}

__global__ void k_bias(const float* b_ih0, const float* b_hh0,
                       const float* b_ih1, const float* b_hh1) {
    int i = blockIdx.x * blockDim.x + threadIdx.x;
    if (i < G4) {
        int c = gate_perm(i);
        g_bias0[c] = b_ih0[i] + b_hh0[i];
        g_bias1[c] = b_ih1[i] + b_hh1[i];
    }
}

__global__ void k_init() {
    int i = blockIdx.x * blockDim.x + threadIdx.x;
    if (i < BATCH * KSPL) {
        __nv_bfloat16 z = __float2bfloat16(0.0f);
        g_h0s[0][i] = z; g_h1s[0][i] = z;
    }
}

// -------------------- cp.async 4-stage pipelined GEMM -----------------------
// C[BM,BN] += A[BM,KSPL] * B[BN,KSPL]^T, row-major bf16, fp32 accum.
// Smem rows padded to 40 bf16 (conflict-free ldmatrix). 4 stages, one
// commit_group per iteration (unconditional -> uniform wait_group counting,
// safe across back-to-back calls).
template <int BM, int BN, int WR, int WC, int NTH>
DI void gemm_cp(const __nv_bfloat16* __restrict__ Ab,
                const __nv_bfloat16* __restrict__ Bm,
                float* acc, __nv_bfloat16* sA, __nv_bfloat16* sB) {
    constexpr int WTM = BM / WR, WTN = BN / WC;
    constexpr int MT = WTM / 16, NG = WTN / 16;
    constexpr int AV = BM * 4 / NTH, BV = BN * 4 / NTH;
    constexpr int NITER = KSPL / 32;
    constexpr int SZA = BM * 40, SZB = BN * 40;
    const int tid = threadIdx.x;
    const int warp = tid >> 5, lane = tid & 31;
    const int wm = warp % WR, wn = warp / WR;
    const int lr = lane & 15, lc = (lane >> 4) << 3;

    // prologue: stages 0..2
#pragma unroll
    for (int s = 0; s < 3; s++) {
#pragma unroll
        for (int i = 0; i < AV; i++) {
            int v = tid + i * NTH;
            cp16(sA + s * SZA + (v >> 2) * 40 + ((v & 3) << 3),
                 Ab + (size_t)(v >> 2) * KSPL + s * 32 + ((v & 3) << 3));
        }
#pragma unroll
        for (int i = 0; i < BV; i++) {
            int v = tid + i * NTH;
            cp16(sB + s * SZB + (v >> 2) * 40 + ((v & 3) << 3),
                 Bm + (size_t)(v >> 2) * KSPL + s * 32 + ((v & 3) << 3));
        }
        cp_commit();
    }

    for (int it = 0; it < NITER; it++) {
        cp_wait2();
        __syncthreads();
        if (it + 3 < NITER) {
            int st = (it + 3) & 3, k0 = (it + 3) * 32;
#pragma unroll
            for (int i = 0; i < AV; i++) {
                int v = tid + i * NTH;
                cp16(sA + st * SZA + (v >> 2) * 40 + ((v & 3) << 3),
                     Ab + (size_t)(v >> 2) * KSPL + k0 + ((v & 3) << 3));
            }
#pragma unroll
            for (int i = 0; i < BV; i++) {
                int v = tid + i * NTH;
                cp16(sB + st * SZB + (v >> 2) * 40 + ((v & 3) << 3),
                     Bm + (size_t)(v >> 2) * KSPL + k0 + ((v & 3) << 3));
            }
        }
        cp_commit();
        const __nv_bfloat16* cA = sA + (it & 3) * SZA;
        const __nv_bfloat16* cB = sB + (it & 3) * SZB;
#pragma unroll
        for (int kk = 0; kk < 32; kk += 16) {
            uint32_t ra[MT][4], rb[NG][4];
#pragma unroll
            for (int mi = 0; mi < MT; mi++)
                ldsm4(ra[mi], cA + (wm * WTM + mi * 16 + lr) * 40 + kk + lc);
#pragma unroll
            for (int ng = 0; ng < NG; ng++)
                ldsm4(rb[ng], cB + (wn * WTN + ng * 16 + lr) * 40 + kk + lc);
#pragma unroll
            for (int mi = 0; mi < MT; mi++)
#pragma unroll
                for (int ng = 0; ng < NG; ng++) {
                    mma16816(acc + ((mi * 2 * NG) + 2 * ng) * 4,     ra[mi], rb[ng][0], rb[ng][2]);
                    mma16816(acc + ((mi * 2 * NG) + 2 * ng + 1) * 4, ra[mi], rb[ng][1], rb[ng][3]);
                }
        }
        // no trailing sync: next iter's wait+syncthreads orders buffer reuse.
    }
}

// --------------------------- precompute big GEMM ----------------------------
// gates_x[t][b][c] = (x[b][t] @ Wih0'^T)[c] + bias0'[c]   (c = permuted col)
constexpr int PRE_SMEM = 2 * 4 * 128 * 40 * (int)sizeof(__nv_bfloat16); // 81920

__global__ void __launch_bounds__(256) k_gemm_pre() {
    extern __shared__ __nv_bfloat16 smem[];
    __nv_bfloat16* sA = smem;
    __nv_bfloat16* sB = smem + 4 * 128 * 40;
    const int m0 = blockIdx.y * 128, n0 = blockIdx.x * 128;
    float acc[64];
#pragma unroll
    for (int i = 0; i < 64; i++) acc[i] = 0.0f;

    gemm_cp<128, 128, 4, 2, 256>(g_xs + (size_t)m0 * KSPL,
                                 g_Wih0s + (size_t)n0 * KSPL, acc, sA, sB);

    const int lane = threadIdx.x & 31, warp = threadIdx.x >> 5;
    const int wm = warp % 4, wn = warp / 4;
#pragma unroll
    for (int mi = 0; mi < 2; mi++)
#pragma unroll
        for (int nt = 0; nt < 8; nt++) {
            float* a4 = acc + ((mi * 8) + nt) * 4;
            int r = m0 + wm * 32 + mi * 16 + (lane >> 2);
            int c = n0 + wn * 64 + nt * 8 + ((lane & 3) << 1);
            {
                int b = r >> 8, t = r & 255;
                size_t d = (size_t)(t * BATCH + b) * G4 + c;
                g_gates_x[d]     = a4[0] + g_bias0[c];
                g_gates_x[d + 1] = a4[1] + g_bias0[c + 1];
            }
            {
                int r2 = r + 8;
                int b = r2 >> 8, t = r2 & 255;
                size_t d = (size_t)(t * BATCH + b) * G4 + c;
                g_gates_x[d]     = a4[2] + g_bias0[c];
                g_gates_x[d + 1] = a4[3] + g_bias0[c + 1];
            }
        }
}

// ----------------------- persistent scan (1 kernel) -------------------------
// 128 CTAs x 256 threads. CTA (bid): m0=(bid&1)*64 rows, n0=(bid>>1)*64 cols
// (= 16 h-columns x 4 gates). Per step:
//   A: gates0 tile = h0[p] @ Whh0' + gates_x[t]; fused cell0 -> h0[p^1], c0 smem
//   grid_bar
//   B: gates1 tile = h0[p^1] @ Wih1' + h1[p] @ Whh1' + bias1'; fused cell1
//      -> h1[p^1], c1 smem, out[:,t,:]
// The single barrier per step orders all cross-CTA hazards (h buffers are
// parity double-buffered; each buffer is written in one phase and only read
// on the other side of a barrier instance).
constexpr int SCAN_SMEM = 2 * 4 * 64 * 40 * (int)sizeof(__nv_bfloat16)  // 40960
                        + 64 * 68 * (int)sizeof(float)                  // 17408
                        + 2 * 1024 * (int)sizeof(float);                // 8192

__global__ void __launch_bounds__(256) k_scan(float* __restrict__ out) {
    extern __shared__ __nv_bfloat16 smem[];
    __nv_bfloat16* sA = smem;                       // 4 stages * 64*40
    __nv_bfloat16* sB = smem + 4 * 64 * 40;
    float* sAcc = (float*)(smem + 8 * 64 * 40);     // 64 x 68
    float* sC   = sAcc + 64 * 68;                   // [2][1024] cell state

    const int bid = blockIdx.x, tid = threadIdx.x;
    const int m0 = (bid & 1) * 64;
    const int n0 = (bid >> 1) * 64;
    const int j0 = n0 >> 2;                         // 16 h-cols per CTA
    const int lane = tid & 31, warp = tid >> 5;
    const int wm = warp & 1, wn = warp >> 1;

    for (int i = tid; i < 2048; i += 256) sC[i] = 0.0f;
    __syncthreads();

    for (int t = 0; t < SEQ; t++) {
        const int p = t & 1;
        float acc[16];

        // ---------------- Phase A: layer-0 GEMM + cell ----------------
#pragma unroll
        for (int i = 0; i < 16; i++) acc[i] = 0.0f;
        gemm_cp<64, 64, 2, 4, 256>(g_h0s[p] + (size_t)m0 * KSPL,
                                   g_Whh0s + (size_t)n0 * KSPL, acc, sA, sB);
        {
            const float* gx = g_gates_x + ((size_t)t * BATCH + m0) * G4 + n0;
#pragma unroll
            for (int mi = 0; mi < 2; mi++)
#pragma unroll
                for (int hf = 0; hf < 2; hf++) {
                    const float* a4 = acc + (mi * 2 + hf) * 4;
                    int r = wm * 32 + mi * 16 + (lane >> 2);
                    int c = wn * 16 + hf * 8 + ((lane & 3) << 1);
                    sAcc[r * 68 + c]           = a4[0] + gx[(size_t)r * G4 + c];
                    sAcc[r * 68 + c + 1]       = a4[1] + gx[(size_t)r * G4 + c + 1];
                    sAcc[(r + 8) * 68 + c]     = a4[2] + gx[(size_t)(r + 8) * G4 + c];
                    sAcc[(r + 8) * 68 + c + 1] = a4[3] + gx[(size_t)(r + 8) * G4 + c + 1];
                }
        }
        __syncthreads();
        {
            __nv_bfloat16* hb = g_h0s[p ^ 1];
#pragma unroll
            for (int e = 0; e < 4; e++) {
                int idx = tid + e * 256;
                int r = idx >> 4, jj = idx & 15;
                float iv = sigf (sAcc[r * 68 + jj]);
                float fv = sigf (sAcc[r * 68 + 16 + jj]);
                float gv = tanhf(sAcc[r * 68 + 32 + jj]);
                float ov = sigf (sAcc[r * 68 + 48 + jj]);
                float cn = fv * sC[idx] + iv * gv;
                sC[idx] = cn;
                float h = ov * tanhf(cn);
                __nv_bfloat16 hi = __float2bfloat16(h);
                __nv_bfloat16 lo = __float2bfloat16(h - __bfloat162float(hi));
                __nv_bfloat16* row = hb + (size_t)(m0 + r) * KSPL + j0 + jj;
                row[0] = hi; row[1024] = hi; row[2048] = lo;
            }
        }
        grid_bar();

        // ---------------- Phase B: layer-1 GEMMs + cell ----------------
#pragma unroll
        for (int i = 0; i < 16; i++) acc[i] = 0.0f;
        gemm_cp<64, 64, 2, 4, 256>(g_h0s[p ^ 1] + (size_t)m0 * KSPL,
                                   g_Wih1s + (size_t)n0 * KSPL, acc, sA, sB);
        gemm_cp<64, 64, 2, 4, 256>(g_h1s[p] + (size_t)m0 * KSPL,
                                   g_Whh1s + (size_t)n0 * KSPL, acc, sA, sB);
        {
#pragma unroll
            for (int mi = 0; mi < 2; mi++)
#pragma unroll
                for (int hf = 0; hf < 2; hf++) {
                    const float* a4 = acc + (mi * 2 + hf) * 4;
                    int r = wm * 32 + mi * 16 + (lane >> 2);
                    int c = wn * 16 + hf * 8 + ((lane & 3) << 1);
                    sAcc[r * 68 + c]           = a4[0] + g_bias1[n0 + c];
                    sAcc[r * 68 + c + 1]       = a4[1] + g_bias1[n0 + c + 1];
                    sAcc[(r + 8) * 68 + c]     = a4[2] + g_bias1[n0 + c];
                    sAcc[(r + 8) * 68 + c + 1] = a4[3] + g_bias1[n0 + c + 1];
                }
        }
        __syncthreads();
        {
            __nv_bfloat16* hb = g_h1s[p ^ 1];
            float* cs = sC + 1024;
            float* op = out + (size_t)t * HDIM + j0;
#pragma unroll
            for (int e = 0; e < 4; e++) {
                int idx = tid + e * 256;
                int r = idx >> 4, jj = idx & 15;
                float iv = sigf (sAcc[r * 68 + jj]);
                float fv = sigf (sAcc[r * 68 + 16 + jj]);
                float gv = tanhf(sAcc[r * 68 + 32 + jj]);
                float ov = sigf (sAcc[r * 68 + 48 + jj]);
                float cn = fv * cs[idx] + iv * gv;
                cs[idx] = cn;
                float h = ov * tanhf(cn);
                __nv_bfloat16 hi = __float2bfloat16(h);
                __nv_bfloat16 lo = __float2bfloat16(h - __bfloat162float(hi));
                __nv_bfloat16* row = hb + (size_t)(m0 + r) * KSPL + j0 + jj;
                row[0] = hi; row[1024] = hi; row[2048] = lo;
                op[(size_t)(m0 + r) * SEQ * HDIM + jj] = h;
            }
        }
        // no barrier here: phase A(t+1) reads h0s[p^1] (written in A(t), which
        // is ordered by bar(t)); its writes target h0s[p], read by nobody
        // after B(t-1). B(t)'s h1s[p^1] writes are ordered before any B(t+1)
        // read by bar(t+1). Cell reads of sAcc finish before the next gemm's
        // first internal __syncthreads.
    }
}

// -------------------------------- launcher ----------------------------------
extern "C" void kernel_launch(void* const* d_in, const int* in_sizes, int n_in,
                              void* d_out, int out_size) {
    const float* x     = (const float*)d_in[0];
    const float* W_ih0 = (const float*)d_in[1];
    const float* b_ih0 = (const float*)d_in[2];
    const float* W_hh0 = (const float*)d_in[3];
    const float* b_hh0 = (const float*)d_in[4];
    const float* W_ih1 = (const float*)d_in[5];
    const float* b_ih1 = (const float*)d_in[6];
    const float* W_hh1 = (const float*)d_in[7];
    const float* b_hh1 = (const float*)d_in[8];
    float* out = (float*)d_out;

    cudaFuncSetAttribute(k_gemm_pre, cudaFuncAttributeMaxDynamicSharedMemorySize, PRE_SMEM);
    cudaFuncSetAttribute(k_scan,     cudaFuncAttributeMaxDynamicSharedMemorySize, SCAN_SMEM);

    // prep (4 nodes)
    k_split_w<<<(4 * G4 * FDIM + 255) / 256, 256>>>(W_ih0, W_hh0, W_ih1, W_hh1);
    k_bias<<<(G4 + 255) / 256, 256>>>(b_ih0, b_hh0, b_ih1, b_hh1);
    k_split_x<<<(MTOT * FDIM + 255) / 256, 256>>>(x);
    k_init<<<(BATCH * KSPL + 255) / 256, 256>>>();

    // big input-projection GEMM, all timesteps (1 node)
    k_gemm_pre<<<dim3(G4 / 128, MTOT / 128), 256, PRE_SMEM>>>();

    // persistent sequential scan (1 node)
    k_scan<<<NCTA, 256, SCAN_SMEM>>>(out);
}

// round 11
// speedup vs baseline: 2.1408x; 1.1618x over previous
#include <cuda_runtime.h>
#include <cuda_bf16.h>
#include <cstdint>
#include <math.h>

// ---------------------------------------------------------------------------
// CustomLSTM: 2-layer LSTM, B=128, T=256, F=H=1024.
// Round 11:
//   * Split-bf16 3-term GEMMs, now in COMPACT 2048-col layout: A=[Ah|Al],
//     B=[Bh|Bl]; inner loop computes AhBh + AhBl + AlBh by pairing hi/lo
//     tiles -> 33% less L2/DRAM traffic than the old [Ah|Ah|Al] layout,
//     bit-identical accumulation terms.
//   * Phase-B's two GEMMs fused into one pipelined loop (2 K-segments).
//   * Persistent scan, 128 CTAs, 1 grid barrier/step (unchanged from R9).
// ---------------------------------------------------------------------------

#define DI __device__ __forceinline__

constexpr int BATCH = 128;
constexpr int SEQ   = 256;
constexpr int FDIM  = 1024;
constexpr int HDIM  = 1024;
constexpr int G4    = 4096;          // 4*H
constexpr int KS    = 2048;          // compact split width [hi|lo]
constexpr int MTOT  = BATCH * SEQ;   // 32768
constexpr int NCTA  = 128;           // persistent scan CTAs
constexpr int SSTR  = 72;            // smem row stride (64 data + 8 pad), bf16

// ------------------------- device scratch (globals) ------------------------
__device__ __nv_bfloat16 g_Wih0s[(size_t)G4 * KS];
__device__ __nv_bfloat16 g_Whh0s[(size_t)G4 * KS];
__device__ __nv_bfloat16 g_Wih1s[(size_t)G4 * KS];
__device__ __nv_bfloat16 g_Whh1s[(size_t)G4 * KS];
__device__ __nv_bfloat16 g_xs[(size_t)MTOT * KS];             // split x [hi|lo]
__device__ float         g_gates_x[(size_t)SEQ * BATCH * G4]; // [t][b][c] permuted
__device__ __nv_bfloat16 g_h0s[2][(size_t)BATCH * KS];        // double-buffered
__device__ __nv_bfloat16 g_h1s[2][(size_t)BATCH * KS];
__device__ float         g_bias0[G4];   // permuted
__device__ float         g_bias1[G4];   // permuted

// software grid barrier (gen monotonic across replays; cnt self-resets)
__device__ unsigned g_bar_cnt;
__device__ unsigned g_bar_gen;

// ------------------------------ small helpers ------------------------------
DI float sigf(float x) { return 1.0f / (1.0f + __expf(-x)); }

// gate-interleave permutation: orig row n = gate*1024 + j ->
// col c = (j/16)*64 + gate*16 + (j%16). 64-col tile = [i|f|g|o] x 16 h-cols.
DI int gate_perm(int n) {
    int g = n >> 10, j = n & 1023;
    return ((j >> 4) << 6) + (g << 4) + (j & 15);
}

DI void ldsm4(uint32_t* r, const __nv_bfloat16* p) {
    uint32_t a = (uint32_t)__cvta_generic_to_shared(p);
    asm volatile("ldmatrix.sync.aligned.m8n8.x4.shared.b16 {%0,%1,%2,%3}, [%4];"
                 : "=r"(r[0]), "=r"(r[1]), "=r"(r[2]), "=r"(r[3]) : "r"(a));
}

DI void mma16816(float* d, const uint32_t* a, uint32_t b0, uint32_t b1) {
    asm volatile(
        "mma.sync.aligned.m16n8k16.row.col.f32.bf16.bf16.f32 "
        "{%0,%1,%2,%3}, {%4,%5,%6,%7}, {%8,%9}, {%0,%1,%2,%3};"
        : "+f"(d[0]), "+f"(d[1]), "+f"(d[2]), "+f"(d[3])
        : "r"(a[0]), "r"(a[1]), "r"(a[2]), "r"(a[3]), "r"(b0), "r"(b1));
}

DI void cp16(void* dst, const void* src) {
    uint32_t d = (uint32_t)__cvta_generic_to_shared(dst);
    asm volatile("cp.async.cg.shared.global [%0], [%1], 16;\n" :: "r"(d), "l"(src));
}
DI void cp_commit() { asm volatile("cp.async.commit_group;\n" ::: "memory"); }
DI void cp_wait2()  { asm volatile("cp.async.wait_group 2;\n"  ::: "memory"); }

DI void grid_bar() {
    __syncthreads();
    if (threadIdx.x == 0) {
        unsigned gen = *(volatile unsigned*)&g_bar_gen;
        __threadfence();
        if (atomicAdd(&g_bar_cnt, 1u) == NCTA - 1u) {
            atomicExch(&g_bar_cnt, 0u);
            __threadfence();
            atomicExch(&g_bar_gen, gen + 1u);
        } else {
            while (*(volatile unsigned*)&g_bar_gen == gen) { __nanosleep(32); }
        }
        __threadfence();
    }
    __syncthreads();
}

// --------------------------- prep / split kernels ---------------------------
__global__ void k_split_w(const float* __restrict__ W0, const float* __restrict__ W1,
                          const float* __restrict__ W2, const float* __restrict__ W3) {
    size_t idx = (size_t)blockIdx.x * blockDim.x + threadIdx.x;
    if (idx >= (size_t)4 * G4 * FDIM) return;
    int which = (int)(idx >> 22);
    int r = (int)(idx & 4194303);
    const float* W = which == 0 ? W0 : which == 1 ? W1 : which == 2 ? W2 : W3;
    __nv_bfloat16* Ws = which == 0 ? g_Wih0s : which == 1 ? g_Whh0s
                       : which == 2 ? g_Wih1s : g_Whh1s;
    int n = r >> 10, k = r & 1023;
    int c = gate_perm(n);
    float v = W[r];
    __nv_bfloat16 hi = __float2bfloat16(v);
    __nv_bfloat16 lo = __float2bfloat16(v - __bfloat162float(hi));
    __nv_bfloat16* row = Ws + (size_t)c * KS;
    row[k] = hi; row[1024 + k] = lo;                      // [Bh | Bl]
}

__global__ void k_split_x(const float* __restrict__ x) {
    size_t idx = (size_t)blockIdx.x * blockDim.x + threadIdx.x;
    if (idx >= (size_t)MTOT * FDIM) return;
    int m = (int)(idx >> 10), k = (int)(idx & 1023);
    float v = x[idx];
    __nv_bfloat16 hi = __float2bfloat16(v);
    __nv_bfloat16 lo = __float2bfloat16(v - __bfloat162float(hi));
    __nv_bfloat16* row = g_xs + (size_t)m * KS;
    row[k] = hi; row[1024 + k] = lo;                      // [Ah | Al]
}

__global__ void k_bias(const float* b_ih0, const float* b_hh0,
                       const float* b_ih1, const float* b_hh1) {
    int i = blockIdx.x * blockDim.x + threadIdx.x;
    if (i < G4) {
        int c = gate_perm(i);
        g_bias0[c] = b_ih0[i] + b_hh0[i];
        g_bias1[c] = b_ih1[i] + b_hh1[i];
    }
}

__global__ void k_init() {
    int i = blockIdx.x * blockDim.x + threadIdx.x;
    if (i < BATCH * KS) {
        __nv_bfloat16 z = __float2bfloat16(0.0f);
        g_h0s[0][i] = z; g_h1s[0][i] = z;
    }
}

// ------------- cp.async 4-stage pipelined split-bf16 GEMM -------------------
// acc += sum over NSEG segments of A_s[BM,1024+1024] x B_s[BN,1024+1024]^T
// computed as AhBh + AhBl + AlBh (fp32 accum). Each 32-wide logical K chunk
// loads 4 subtiles (Ah,Al,Bh,Bl) into one stage: smem row = [hi 32 | lo 32].
// One commit_group per chunk; wait_group 2; single __syncthreads per chunk.
template <int BM, int BN, int WR, int WC, int NTH, int NSEG>
DI void gemm_cp(const __nv_bfloat16* __restrict__ A0,
                const __nv_bfloat16* __restrict__ B0,
                const __nv_bfloat16* __restrict__ A1,
                const __nv_bfloat16* __restrict__ B1,
                float* acc, __nv_bfloat16* sA, __nv_bfloat16* sB) {
    constexpr int WTM = BM / WR, WTN = BN / WC;
    constexpr int MT = WTM / 16, NG = WTN / 16;
    constexpr int AV = BM * 8 / NTH, BV = BN * 8 / NTH;   // cp16 per thread
    constexpr int NITER = NSEG * 32;
    constexpr int SZA = BM * SSTR, SZB = BN * SSTR;
    const int tid = threadIdx.x;
    const int warp = tid >> 5, lane = tid & 31;
    const int wm = warp % WR, wn = warp / WR;
    const int lr = lane & 15, lc = (lane >> 4) << 3;

    auto fetch = [&](int c, int st) {
        const __nv_bfloat16* A = (NSEG == 2 && c >= 32) ? A1 : A0;
        const __nv_bfloat16* B = (NSEG == 2 && c >= 32) ? B1 : B0;
        int k32 = (c & 31) << 5;
#pragma unroll
        for (int i = 0; i < AV; i++) {
            int v = tid + i * NTH;
            int row = v >> 3, rem = v & 7, hf = rem >> 2, cp = (rem & 3) << 3;
            cp16(sA + st * SZA + row * SSTR + (hf << 5) + cp,
                 A + (size_t)row * KS + hf * 1024 + k32 + cp);
        }
#pragma unroll
        for (int i = 0; i < BV; i++) {
            int v = tid + i * NTH;
            int row = v >> 3, rem = v & 7, hf = rem >> 2, cp = (rem & 3) << 3;
            cp16(sB + st * SZB + row * SSTR + (hf << 5) + cp,
                 B + (size_t)row * KS + hf * 1024 + k32 + cp);
        }
        cp_commit();
    };

    // prologue: stages 0..2
#pragma unroll
    for (int s = 0; s < 3; s++) fetch(s, s);

    for (int it = 0; it < NITER; it++) {
        cp_wait2();
        __syncthreads();
        if (it + 3 < NITER) fetch(it + 3, (it + 3) & 3);
        else cp_commit();
        const __nv_bfloat16* cA = sA + (it & 3) * SZA;
        const __nv_bfloat16* cB = sB + (it & 3) * SZB;
#pragma unroll
        for (int kk = 0; kk < 32; kk += 16) {
            uint32_t rah[MT][4], ral[MT][4], rbh[NG][4], rbl[NG][4];
#pragma unroll
            for (int mi = 0; mi < MT; mi++) {
                const __nv_bfloat16* p = cA + (wm * WTM + mi * 16 + lr) * SSTR + kk + lc;
                ldsm4(rah[mi], p);
                ldsm4(ral[mi], p + 32);
            }
#pragma unroll
            for (int ng = 0; ng < NG; ng++) {
                const __nv_bfloat16* p = cB + (wn * WTN + ng * 16 + lr) * SSTR + kk + lc;
                ldsm4(rbh[ng], p);
                ldsm4(rbl[ng], p + 32);
            }
#pragma unroll
            for (int mi = 0; mi < MT; mi++)
#pragma unroll
                for (int ng = 0; ng < NG; ng++) {
                    float* a0 = acc + ((mi * 2 * NG) + 2 * ng) * 4;
                    float* a1 = a0 + 4;
                    mma16816(a0, rah[mi], rbh[ng][0], rbh[ng][2]);
                    mma16816(a1, rah[mi], rbh[ng][1], rbh[ng][3]);
                    mma16816(a0, rah[mi], rbl[ng][0], rbl[ng][2]);
                    mma16816(a1, rah[mi], rbl[ng][1], rbl[ng][3]);
                    mma16816(a0, ral[mi], rbh[ng][0], rbh[ng][2]);
                    mma16816(a1, ral[mi], rbh[ng][1], rbh[ng][3]);
                }
        }
        // no trailing sync: next iter's wait+syncthreads orders buffer reuse.
    }
}

// --------------------------- precompute big GEMM ----------------------------
// gates_x[t][b][c] = (x[b][t] @ Wih0'^T)[c] + bias0'[c]   (c = permuted col)
// Tile 128x128, WR=2/WC=4 -> warptile 64x32, MT=4, NG=2.
constexpr int PRE_SMEM = 4 * (128 + 128) * SSTR * (int)sizeof(__nv_bfloat16); // 147456

__global__ void __launch_bounds__(256) k_gemm_pre() {
    extern __shared__ __nv_bfloat16 smem[];
    __nv_bfloat16* sA = smem;
    __nv_bfloat16* sB = smem + 4 * 128 * SSTR;
    const int m0 = blockIdx.y * 128, n0 = blockIdx.x * 128;
    float acc[64];
#pragma unroll
    for (int i = 0; i < 64; i++) acc[i] = 0.0f;

    gemm_cp<128, 128, 2, 4, 256, 1>(g_xs + (size_t)m0 * KS,
                                    g_Wih0s + (size_t)n0 * KS,
                                    nullptr, nullptr, acc, sA, sB);

    const int lane = threadIdx.x & 31, warp = threadIdx.x >> 5;
    const int wm = warp & 1, wn = warp >> 1;
#pragma unroll
    for (int mi = 0; mi < 4; mi++)
#pragma unroll
        for (int ng = 0; ng < 2; ng++)
#pragma unroll
            for (int hf = 0; hf < 2; hf++) {
                const float* a4 = acc + ((mi * 4) + 2 * ng + hf) * 4;
                int r = m0 + wm * 64 + mi * 16 + (lane >> 2);
                int c = n0 + wn * 32 + ng * 16 + hf * 8 + ((lane & 3) << 1);
                {
                    int b = r >> 8, t = r & 255;
                    size_t d = (size_t)(t * BATCH + b) * G4 + c;
                    g_gates_x[d]     = a4[0] + g_bias0[c];
                    g_gates_x[d + 1] = a4[1] + g_bias0[c + 1];
                }
                {
                    int r2 = r + 8;
                    int b = r2 >> 8, t = r2 & 255;
                    size_t d = (size_t)(t * BATCH + b) * G4 + c;
                    g_gates_x[d]     = a4[2] + g_bias0[c];
                    g_gates_x[d + 1] = a4[3] + g_bias0[c + 1];
                }
            }
}

// ----------------------- persistent scan (1 kernel) -------------------------
// 128 CTAs x 256 threads. CTA: m0=(bid&1)*64 rows, n0=(bid>>1)*64 cols
// (16 h-cols x 4 gates). Per step:
//   A: gates0 = h0[p]@Whh0' + gates_x[t]; fused cell0 -> h0[p^1], c0 in smem
//   grid_bar
//   B: gates1 = h0[p^1]@Wih1' + h1[p]@Whh1' + bias1' (ONE fused 2-seg
//      pipeline); fused cell1 -> h1[p^1], c1 in smem, out[:,t,:]
// Hazards ordered by the single barrier + parity double buffering (see R9/R10
// analysis; layout change doesn't alter the dependence structure).
constexpr int SCAN_SMEM = 4 * (64 + 64) * SSTR * (int)sizeof(__nv_bfloat16)  // 73728
                        + 64 * 68 * (int)sizeof(float)                       // 17408
                        + 2 * 1024 * (int)sizeof(float);                     // 8192

__global__ void __launch_bounds__(256) k_scan(float* __restrict__ out) {
    extern __shared__ __nv_bfloat16 smem[];
    __nv_bfloat16* sA = smem;                          // 4 stages * 64*SSTR
    __nv_bfloat16* sB = smem + 4 * 64 * SSTR;
    float* sAcc = (float*)(smem + 8 * 64 * SSTR);      // 64 x 68
    float* sC   = sAcc + 64 * 68;                      // [2][1024] cell state

    const int bid = blockIdx.x, tid = threadIdx.x;
    const int m0 = (bid & 1) * 64;
    const int n0 = (bid >> 1) * 64;
    const int j0 = n0 >> 2;                            // 16 h-cols per CTA
    const int lane = tid & 31, warp = tid >> 5;
    const int wm = warp & 1, wn = warp >> 1;           // WR=2, WC=4

    for (int i = tid; i < 2048; i += 256) sC[i] = 0.0f;
    __syncthreads();

    for (int t = 0; t < SEQ; t++) {
        const int p = t & 1;
        float acc[16];

        // ---------------- Phase A: layer-0 GEMM + cell ----------------
#pragma unroll
        for (int i = 0; i < 16; i++) acc[i] = 0.0f;
        gemm_cp<64, 64, 2, 4, 256, 1>(g_h0s[p] + (size_t)m0 * KS,
                                      g_Whh0s + (size_t)n0 * KS,
                                      nullptr, nullptr, acc, sA, sB);
        {
            const float* gx = g_gates_x + ((size_t)t * BATCH + m0) * G4 + n0;
#pragma unroll
            for (int mi = 0; mi < 2; mi++)
#pragma unroll
                for (int hf = 0; hf < 2; hf++) {
                    const float* a4 = acc + (mi * 2 + hf) * 4;
                    int r = wm * 32 + mi * 16 + (lane >> 2);
                    int c = wn * 16 + hf * 8 + ((lane & 3) << 1);
                    sAcc[r * 68 + c]           = a4[0] + gx[(size_t)r * G4 + c];
                    sAcc[r * 68 + c + 1]       = a4[1] + gx[(size_t)r * G4 + c + 1];
                    sAcc[(r + 8) * 68 + c]     = a4[2] + gx[(size_t)(r + 8) * G4 + c];
                    sAcc[(r + 8) * 68 + c + 1] = a4[3] + gx[(size_t)(r + 8) * G4 + c + 1];
                }
        }
        __syncthreads();
        {
            __nv_bfloat16* hb = g_h0s[p ^ 1];
#pragma unroll
            for (int e = 0; e < 4; e++) {
                int idx = tid + e * 256;
                int r = idx >> 4, jj = idx & 15;
                float iv = sigf (sAcc[r * 68 + jj]);
                float fv = sigf (sAcc[r * 68 + 16 + jj]);
                float gv = tanhf(sAcc[r * 68 + 32 + jj]);
                float ov = sigf (sAcc[r * 68 + 48 + jj]);
                float cn = fv * sC[idx] + iv * gv;
                sC[idx] = cn;
                float h = ov * tanhf(cn);
                __nv_bfloat16 hi = __float2bfloat16(h);
                __nv_bfloat16 lo = __float2bfloat16(h - __bfloat162float(hi));
                __nv_bfloat16* row = hb + (size_t)(m0 + r) * KS + j0 + jj;
                row[0] = hi; row[1024] = lo;
            }
        }
        grid_bar();

        // ------- Phase B: layer-1 fused 2-segment GEMM + cell ----------
#pragma unroll
        for (int i = 0; i < 16; i++) acc[i] = 0.0f;
        gemm_cp<64, 64, 2, 4, 256, 2>(g_h0s[p ^ 1] + (size_t)m0 * KS,
                                      g_Wih1s + (size_t)n0 * KS,
                                      g_h1s[p] + (size_t)m0 * KS,
                                      g_Whh1s + (size_t)n0 * KS, acc, sA, sB);
        {
#pragma unroll
            for (int mi = 0; mi < 2; mi++)
#pragma unroll
                for (int hf = 0; hf < 2; hf++) {
                    const float* a4 = acc + (mi * 2 + hf) * 4;
                    int r = wm * 32 + mi * 16 + (lane >> 2);
                    int c = wn * 16 + hf * 8 + ((lane & 3) << 1);
                    sAcc[r * 68 + c]           = a4[0] + g_bias1[n0 + c];
                    sAcc[r * 68 + c + 1]       = a4[1] + g_bias1[n0 + c + 1];
                    sAcc[(r + 8) * 68 + c]     = a4[2] + g_bias1[n0 + c];
                    sAcc[(r + 8) * 68 + c + 1] = a4[3] + g_bias1[n0 + c + 1];
                }
        }
        __syncthreads();
        {
            __nv_bfloat16* hb = g_h1s[p ^ 1];
            float* cs = sC + 1024;
            float* op = out + (size_t)t * HDIM + j0;
#pragma unroll
            for (int e = 0; e < 4; e++) {
                int idx = tid + e * 256;
                int r = idx >> 4, jj = idx & 15;
                float iv = sigf (sAcc[r * 68 + jj]);
                float fv = sigf (sAcc[r * 68 + 16 + jj]);
                float gv = tanhf(sAcc[r * 68 + 32 + jj]);
                float ov = sigf (sAcc[r * 68 + 48 + jj]);
                float cn = fv * cs[idx] + iv * gv;
                cs[idx] = cn;
                float h = ov * tanhf(cn);
                __nv_bfloat16 hi = __float2bfloat16(h);
                __nv_bfloat16 lo = __float2bfloat16(h - __bfloat162float(hi));
                __nv_bfloat16* row = hb + (size_t)(m0 + r) * KS + j0 + jj;
                row[0] = hi; row[1024] = lo;
                op[(size_t)(m0 + r) * SEQ * HDIM + jj] = h;
            }
        }
        // no barrier: A(t+1) reads h0s[p^1] (written in A(t), ordered by
        // bar(t)); writes h0s[p] which no concurrent phase reads. B(t)'s
        // h1s[p^1] writes are ordered before B(t+1) reads by bar(t+1).
    }
}

// -------------------------------- launcher ----------------------------------
extern "C" void kernel_launch(void* const* d_in, const int* in_sizes, int n_in,
                              void* d_out, int out_size) {
    const float* x     = (const float*)d_in[0];
    const float* W_ih0 = (const float*)d_in[1];
    const float* b_ih0 = (const float*)d_in[2];
    const float* W_hh0 = (const float*)d_in[3];
    const float* b_hh0 = (const float*)d_in[4];
    const float* W_ih1 = (const float*)d_in[5];
    const float* b_ih1 = (const float*)d_in[6];
    const float* W_hh1 = (const float*)d_in[7];
    const float* b_hh1 = (const float*)d_in[8];
    float* out = (float*)d_out;

    cudaFuncSetAttribute(k_gemm_pre, cudaFuncAttributeMaxDynamicSharedMemorySize, PRE_SMEM);
    cudaFuncSetAttribute(k_scan,     cudaFuncAttributeMaxDynamicSharedMemorySize, SCAN_SMEM);

    // prep (4 nodes)
    k_split_w<<<(4 * G4 * FDIM + 255) / 256, 256>>>(W_ih0, W_hh0, W_ih1, W_hh1);
    k_bias<<<(G4 + 255) / 256, 256>>>(b_ih0, b_hh0, b_ih1, b_hh1);
    k_split_x<<<(MTOT * FDIM + 255) / 256, 256>>>(x);
    k_init<<<(BATCH * KS + 255) / 256, 256>>>();

    // big input-projection GEMM, all timesteps (1 node)
    k_gemm_pre<<<dim3(G4 / 128, MTOT / 128), 256, PRE_SMEM>>>();

    // persistent sequential scan (1 node)
    k_scan<<<NCTA, 256, SCAN_SMEM>>>(out);
}

// round 13
// speedup vs baseline: 2.3131x; 1.0805x over previous
#include <cuda_runtime.h>
#include <cuda_bf16.h>
#include <cstdint>
#include <math.h>

// ---------------------------------------------------------------------------
// CustomLSTM: 2-layer LSTM, B=128, T=256, F=H=1024.
// Round 13:
//   * R12's tcgen05 scan, now guarded for arch-SPECIFIC targets only
//     (sm_103a/sm_100a feature macros). The harness also compiles a plain
//     sm_103 pass where tcgen05 does not exist -> that pass now gets a
//     correct mma.sync fallback with the SAME launch config, so the build
//     succeeds and whichever cubin loads is correct.
//   * Everything else (split-bf16 3-term math, hoisted input projection,
//     gate-permuted tiles, persistent scan w/ 1 grid-bar/step) unchanged.
// ---------------------------------------------------------------------------

#define DI __device__ __forceinline__

// tcgen05 available only in arch-specific device passes (sm_103a etc.)
#if defined(__CUDA_ARCH__) && !(defined(__CUDA_ARCH_FEAT_SM103_ALL) ||       \
    defined(__CUDA_ARCH_FEAT_SM100_ALL) || defined(__CUDA_ARCH_SPECIFIC__) ||\
    defined(__CUDA_ARCH_FAMILY_SPECIFIC__))
#define T5_OK 0
#else
#define T5_OK 1
#endif

constexpr int BATCH = 128;
constexpr int SEQ   = 256;
constexpr int FDIM  = 1024;
constexpr int HDIM  = 1024;
constexpr int G4    = 4096;          // 4*H
constexpr int KS    = 2048;          // compact split width [hi|lo]
constexpr int MTOT  = BATCH * SEQ;   // 32768
constexpr int NCTA  = 64;            // persistent scan CTAs
constexpr int SSTR  = 72;            // smem row stride for mma.sync paths

// scan smem stage layout (bytes) for tcgen05 path
constexpr int STG_AH = 0;            // 128 rows x 128B
constexpr int STG_AL = 16384;
constexpr int STG_BH = 32768;        // 64 rows x 128B
constexpr int STG_BL = 40960;
constexpr int STG_SZ = 49152;        // 48KB per stage
constexpr int SCAN_DYN = 3 * STG_SZ + 1024;   // 148480 (also covers fallback)

// idesc kind::f16: F32 acc, bf16 a/b, N=64, M=128
constexpr uint32_t IDESC_F16 =
    (1u << 4) | (1u << 7) | (1u << 10) | ((64u / 8) << 17) | ((128u / 16) << 24);

// SW128 smem descriptor base (Blackwell): layout=SW128, ver=1, SBO=64, LBO=1
constexpr uint64_t DESC_SW128 =
    (uint64_t(2) << 61) | (uint64_t(1) << 46) | (uint64_t(64) << 32) | (uint64_t(1) << 16);
#define MK_DESC(addr) (DESC_SW128 | ((uint64_t)((addr) >> 4) & 0x3FFF))

// ------------------------- device scratch (globals) ------------------------
__device__ __nv_bfloat16 g_Wih0s[(size_t)G4 * KS];
__device__ __nv_bfloat16 g_Whh0s[(size_t)G4 * KS];
__device__ __nv_bfloat16 g_Wih1s[(size_t)G4 * KS];
__device__ __nv_bfloat16 g_Whh1s[(size_t)G4 * KS];
__device__ __nv_bfloat16 g_xs[(size_t)MTOT * KS];             // split x [hi|lo]
__device__ float         g_gates_x[(size_t)SEQ * BATCH * G4]; // [t][b][c] permuted
__device__ __nv_bfloat16 g_h0s[2][(size_t)BATCH * KS];        // double-buffered
__device__ __nv_bfloat16 g_h1s[2][(size_t)BATCH * KS];
__device__ float         g_bias0[G4];   // permuted
__device__ float         g_bias1[G4];   // permuted

__device__ unsigned g_bar_cnt;
__device__ unsigned g_bar_gen;

// ------------------------------ small helpers ------------------------------
DI float sigf(float x) { return 1.0f / (1.0f + __expf(-x)); }

DI int gate_perm(int n) {            // row n -> permuted col
    int g = n >> 10, j = n & 1023;
    return ((j >> 4) << 6) + (g << 4) + (j & 15);
}

DI uint32_t smem_u32(const void* p) {
    uint32_t a;
    asm("{ .reg .u64 t; cvta.to.shared.u64 t, %1; cvt.u32.u64 %0, t; }"
        : "=r"(a) : "l"(p));
    return a;
}

DI uint32_t elect1() {
    uint32_t p;
    asm volatile("{\n\t.reg .pred p;\n\telect.sync _|p, 0xFFFFFFFF;\n\t"
                 "selp.b32 %0, 1, 0, p;\n\t}" : "=r"(p));
    return p;
}

DI void ldsm4(uint32_t* r, const __nv_bfloat16* p) {
    uint32_t a = (uint32_t)__cvta_generic_to_shared(p);
    asm volatile("ldmatrix.sync.aligned.m8n8.x4.shared.b16 {%0,%1,%2,%3}, [%4];"
                 : "=r"(r[0]), "=r"(r[1]), "=r"(r[2]), "=r"(r[3]) : "r"(a));
}

DI void mma16816(float* d, const uint32_t* a, uint32_t b0, uint32_t b1) {
    asm volatile(
        "mma.sync.aligned.m16n8k16.row.col.f32.bf16.bf16.f32 "
        "{%0,%1,%2,%3}, {%4,%5,%6,%7}, {%8,%9}, {%0,%1,%2,%3};"
        : "+f"(d[0]), "+f"(d[1]), "+f"(d[2]), "+f"(d[3])
        : "r"(a[0]), "r"(a[1]), "r"(a[2]), "r"(a[3]), "r"(b0), "r"(b1));
}

DI void cp16(void* dst, const void* src) {
    uint32_t d = (uint32_t)__cvta_generic_to_shared(dst);
    asm volatile("cp.async.cg.shared.global [%0], [%1], 16;\n" :: "r"(d), "l"(src));
}
DI void cp16s(uint32_t dst, const void* src) {
    asm volatile("cp.async.cg.shared.global [%0], [%1], 16;\n" :: "r"(dst), "l"(src));
}
DI void cp_commit() { asm volatile("cp.async.commit_group;\n" ::: "memory"); }
DI void cp_wait1()  { asm volatile("cp.async.wait_group 1;\n"  ::: "memory"); }
DI void cp_wait2()  { asm volatile("cp.async.wait_group 2;\n"  ::: "memory"); }

DI void grid_bar() {
    __syncthreads();
    if (threadIdx.x == 0) {
        unsigned gen = *(volatile unsigned*)&g_bar_gen;
        __threadfence();
        if (atomicAdd(&g_bar_cnt, 1u) == NCTA - 1u) {
            atomicExch(&g_bar_cnt, 0u);
            __threadfence();
            atomicExch(&g_bar_gen, gen + 1u);
        } else {
            while (*(volatile unsigned*)&g_bar_gen == gen) { __nanosleep(32); }
        }
        __threadfence();
    }
    __syncthreads();
}

// ---------------------------- tcgen05 wrappers ------------------------------
#if T5_OK
#define T5_ALLOC(smem_addr, n) \
    asm volatile("tcgen05.alloc.cta_group::1.sync.aligned.shared::cta.b32 [%0], %1;" \
                 :: "r"(smem_addr), "r"((uint32_t)(n)) : "memory")
#define T5_DEALLOC(tmem, n) \
    asm volatile("tcgen05.dealloc.cta_group::1.sync.aligned.b32 %0, %1;" \
                 :: "r"(tmem), "r"((uint32_t)(n)))
#define T5_RELINQ() \
    asm volatile("tcgen05.relinquish_alloc_permit.cta_group::1.sync.aligned;")
#define T5_COMMIT(mb) \
    asm volatile("tcgen05.commit.cta_group::1.mbarrier::arrive::one.shared::cluster.b64 [%0];" \
                 :: "r"(mb) : "memory")
#define T5_FENCE_AFTER()  asm volatile("tcgen05.fence::after_thread_sync;" ::: "memory")
#define T5_FENCE_BEFORE() asm volatile("tcgen05.fence::before_thread_sync;" ::: "memory")
#define T5_WAIT_LD()      asm volatile("tcgen05.wait::ld.sync.aligned;" ::: "memory")

#define MBAR_INIT(mb, cnt) \
    asm volatile("mbarrier.init.shared.b64 [%0], %1;" :: "r"(mb), "r"((uint32_t)(cnt)) : "memory")

#define MBAR_WAIT(mb, par) do {                                              \
    uint32_t _mb = (mb), _pp = (par), _done;                                 \
    asm volatile("{\n\t.reg .pred p;\n\t"                                    \
        "mbarrier.try_wait.parity.acquire.cta.shared::cta.b64 p, [%1], %2;\n\t" \
        "selp.b32 %0, 1, 0, p;\n\t}" : "=r"(_done) : "r"(_mb), "r"(_pp) : "memory"); \
    if (!_done) {                                                            \
        asm volatile("{\n\t.reg .pred P1;\n\t"                               \
            "WL_%=:\n\t"                                                     \
            "mbarrier.try_wait.parity.acquire.cta.shared::cta.b64 P1, [%0], %1, 0x989680;\n\t" \
            "@P1 bra.uni WD_%=;\n\t"                                         \
            "bra.uni WL_%=;\n\t"                                             \
            "WD_%=:\n\t}" :: "r"(_mb), "r"(_pp) : "memory");                 \
    }                                                                        \
} while (0)

#define T5_LD_X32(r, tm)                                                     \
    asm volatile("tcgen05.ld.sync.aligned.32x32b.x32.b32 "                   \
        "{%0, %1, %2, %3, %4, %5, %6, %7, "                                  \
        " %8, %9, %10, %11, %12, %13, %14, %15, "                            \
        " %16, %17, %18, %19, %20, %21, %22, %23, "                          \
        " %24, %25, %26, %27, %28, %29, %30, %31}, [%32];"                   \
        : "=r"((r)[0]),  "=r"((r)[1]),  "=r"((r)[2]),  "=r"((r)[3]),         \
          "=r"((r)[4]),  "=r"((r)[5]),  "=r"((r)[6]),  "=r"((r)[7]),         \
          "=r"((r)[8]),  "=r"((r)[9]),  "=r"((r)[10]), "=r"((r)[11]),        \
          "=r"((r)[12]), "=r"((r)[13]), "=r"((r)[14]), "=r"((r)[15]),        \
          "=r"((r)[16]), "=r"((r)[17]), "=r"((r)[18]), "=r"((r)[19]),        \
          "=r"((r)[20]), "=r"((r)[21]), "=r"((r)[22]), "=r"((r)[23]),        \
          "=r"((r)[24]), "=r"((r)[25]), "=r"((r)[26]), "=r"((r)[27]),        \
          "=r"((r)[28]), "=r"((r)[29]), "=r"((r)[30]), "=r"((r)[31])         \
        : "r"(tm))

DI void mma_f16_ss(uint32_t d, uint64_t a, uint64_t b, uint32_t en) {
    asm volatile(
        "{\n\t.reg .pred p;\n\tsetp.ne.u32 p, %4, 0;\n\t"
        "tcgen05.mma.cta_group::1.kind::f16 [%0], %1, %2, %3, {%5,%5,%5,%5}, p;\n\t}"
        :: "r"(d), "l"(a), "l"(b), "r"(IDESC_F16), "r"(en), "r"(0u) : "memory");
}
#endif  // T5_OK

// --------------------------- prep / split kernels ---------------------------
__global__ void k_split_w(const float* __restrict__ W0, const float* __restrict__ W1,
                          const float* __restrict__ W2, const float* __restrict__ W3) {
    size_t idx = (size_t)blockIdx.x * blockDim.x + threadIdx.x;
    if (idx >= (size_t)4 * G4 * FDIM) return;
    int which = (int)(idx >> 22);
    int r = (int)(idx & 4194303);
    const float* W = which == 0 ? W0 : which == 1 ? W1 : which == 2 ? W2 : W3;
    __nv_bfloat16* Ws = which == 0 ? g_Wih0s : which == 1 ? g_Whh0s
                       : which == 2 ? g_Wih1s : g_Whh1s;
    int n = r >> 10, k = r & 1023;
    int c = gate_perm(n);
    float v = W[r];
    __nv_bfloat16 hi = __float2bfloat16(v);
    __nv_bfloat16 lo = __float2bfloat16(v - __bfloat162float(hi));
    __nv_bfloat16* row = Ws + (size_t)c * KS;
    row[k] = hi; row[1024 + k] = lo;
}

__global__ void k_split_x(const float* __restrict__ x) {
    size_t idx = (size_t)blockIdx.x * blockDim.x + threadIdx.x;
    if (idx >= (size_t)MTOT * FDIM) return;
    int m = (int)(idx >> 10), k = (int)(idx & 1023);
    float v = x[idx];
    __nv_bfloat16 hi = __float2bfloat16(v);
    __nv_bfloat16 lo = __float2bfloat16(v - __bfloat162float(hi));
    __nv_bfloat16* row = g_xs + (size_t)m * KS;
    row[k] = hi; row[1024 + k] = lo;
}

__global__ void k_bias(const float* b_ih0, const float* b_hh0,
                       const float* b_ih1, const float* b_hh1) {
    int i = blockIdx.x * blockDim.x + threadIdx.x;
    if (i < G4) {
        int c = gate_perm(i);
        g_bias0[c] = b_ih0[i] + b_hh0[i];
        g_bias1[c] = b_ih1[i] + b_hh1[i];
    }
}

__global__ void k_init() {
    int i = blockIdx.x * blockDim.x + threadIdx.x;
    if (i < BATCH * KS) {
        __nv_bfloat16 z = __float2bfloat16(0.0f);
        g_h0s[0][i] = z; g_h1s[0][i] = z;
    }
}

// ------------- mma.sync cp.async 4-stage pipeline (pre-GEMM + fallback) -----
template <int BM, int BN, int WR, int WC, int NTH>
DI void gemm_cp(const __nv_bfloat16* __restrict__ A0,
                const __nv_bfloat16* __restrict__ B0,
                float* acc, __nv_bfloat16* sA, __nv_bfloat16* sB) {
    constexpr int WTM = BM / WR, WTN = BN / WC;
    constexpr int MT = WTM / 16, NG = WTN / 16;
    constexpr int AV = BM * 8 / NTH, BV = BN * 8 / NTH;
    constexpr int NITER = 32;
    constexpr int SZA = BM * SSTR, SZB = BN * SSTR;
    const int tid = threadIdx.x;
    const int warp = tid >> 5, lane = tid & 31;
    const int wm = warp % WR, wn = warp / WR;
    const int lr = lane & 15, lc = (lane >> 4) << 3;

    auto fetch = [&](int c, int st) {
        int k32 = c << 5;
#pragma unroll
        for (int i = 0; i < AV; i++) {
            int v = tid + i * NTH;
            int row = v >> 3, rem = v & 7, hf = rem >> 2, cp = (rem & 3) << 3;
            cp16(sA + st * SZA + row * SSTR + (hf << 5) + cp,
                 A0 + (size_t)row * KS + hf * 1024 + k32 + cp);
        }
#pragma unroll
        for (int i = 0; i < BV; i++) {
            int v = tid + i * NTH;
            int row = v >> 3, rem = v & 7, hf = rem >> 2, cp = (rem & 3) << 3;
            cp16(sB + st * SZB + row * SSTR + (hf << 5) + cp,
                 B0 + (size_t)row * KS + hf * 1024 + k32 + cp);
        }
        cp_commit();
    };

#pragma unroll
    for (int s = 0; s < 3; s++) fetch(s, s);

    for (int it = 0; it < NITER; it++) {
        cp_wait2();
        __syncthreads();
        if (it + 3 < NITER) fetch(it + 3, (it + 3) & 3);
        else cp_commit();
        const __nv_bfloat16* cA = sA + (it & 3) * SZA;
        const __nv_bfloat16* cB = sB + (it & 3) * SZB;
#pragma unroll
        for (int kk = 0; kk < 32; kk += 16) {
            uint32_t rah[MT][4], ral[MT][4], rbh[NG][4], rbl[NG][4];
#pragma unroll
            for (int mi = 0; mi < MT; mi++) {
                const __nv_bfloat16* p = cA + (wm * WTM + mi * 16 + lr) * SSTR + kk + lc;
                ldsm4(rah[mi], p);
                ldsm4(ral[mi], p + 32);
            }
#pragma unroll
            for (int ng = 0; ng < NG; ng++) {
                const __nv_bfloat16* p = cB + (wn * WTN + ng * 16 + lr) * SSTR + kk + lc;
                ldsm4(rbh[ng], p);
                ldsm4(rbl[ng], p + 32);
            }
#pragma unroll
            for (int mi = 0; mi < MT; mi++)
#pragma unroll
                for (int ng = 0; ng < NG; ng++) {
                    float* a0 = acc + ((mi * 2 * NG) + 2 * ng) * 4;
                    float* a1 = a0 + 4;
                    mma16816(a0, rah[mi], rbh[ng][0], rbh[ng][2]);
                    mma16816(a1, rah[mi], rbh[ng][1], rbh[ng][3]);
                    mma16816(a0, rah[mi], rbl[ng][0], rbl[ng][2]);
                    mma16816(a1, rah[mi], rbl[ng][1], rbl[ng][3]);
                    mma16816(a0, ral[mi], rbh[ng][0], rbh[ng][2]);
                    mma16816(a1, ral[mi], rbh[ng][1], rbh[ng][3]);
                }
        }
    }
}

constexpr int PRE_SMEM = 4 * (128 + 128) * SSTR * (int)sizeof(__nv_bfloat16);

__global__ void __launch_bounds__(256) k_gemm_pre() {
    extern __shared__ __nv_bfloat16 smem[];
    __nv_bfloat16* sA = smem;
    __nv_bfloat16* sB = smem + 4 * 128 * SSTR;
    const int m0 = blockIdx.y * 128, n0 = blockIdx.x * 128;
    float acc[64];
#pragma unroll
    for (int i = 0; i < 64; i++) acc[i] = 0.0f;

    gemm_cp<128, 128, 2, 4, 256>(g_xs + (size_t)m0 * KS,
                                 g_Wih0s + (size_t)n0 * KS, acc, sA, sB);

    const int lane = threadIdx.x & 31, warp = threadIdx.x >> 5;
    const int wm = warp & 1, wn = warp >> 1;
#pragma unroll
    for (int mi = 0; mi < 4; mi++)
#pragma unroll
        for (int ng = 0; ng < 2; ng++)
#pragma unroll
            for (int hf = 0; hf < 2; hf++) {
                const float* a4 = acc + ((mi * 4) + 2 * ng + hf) * 4;
                int r = m0 + wm * 64 + mi * 16 + (lane >> 2);
                int c = n0 + wn * 32 + ng * 16 + hf * 8 + ((lane & 3) << 1);
                {
                    int b = r >> 8, t = r & 255;
                    size_t d = (size_t)(t * BATCH + b) * G4 + c;
                    g_gates_x[d]     = a4[0] + g_bias0[c];
                    g_gates_x[d + 1] = a4[1] + g_bias0[c + 1];
                }
                {
                    int r2 = r + 8;
                    int b = r2 >> 8, t = r2 & 255;
                    size_t d = (size_t)(t * BATCH + b) * G4 + c;
                    g_gates_x[d]     = a4[2] + g_bias0[c];
                    g_gates_x[d + 1] = a4[3] + g_bias0[c + 1];
                }
            }
}

// -------------------------- scan: tcgen05 pieces ----------------------------
#if T5_OK
// Load one 64-col K-chunk (Ah/Al 128 rows, Bh/Bl 64 rows) into stage `st`.
DI void load_chunk(uint32_t st, const __nv_bfloat16* __restrict__ A,
                   const __nv_bfloat16* __restrict__ B, int kc, int tid) {
    const int kb = kc << 6;   // bf16 col base
#pragma unroll
    for (int i = 0; i < 24; i++) {
        int v = tid + (i << 7);
        uint32_t dst; const __nv_bfloat16* src;
        if (v < 1024) {
            int row = v >> 3, c = v & 7;
            uint32_t off = (uint32_t)(row * 128 + c * 16);
            dst = st + STG_AH + (off ^ ((off >> 3) & 0x70));
            src = A + (size_t)row * KS + kb + c * 8;
        } else if (v < 2048) {
            int w = v - 1024, row = w >> 3, c = w & 7;
            uint32_t off = (uint32_t)(row * 128 + c * 16);
            dst = st + STG_AL + (off ^ ((off >> 3) & 0x70));
            src = A + (size_t)row * KS + 1024 + kb + c * 8;
        } else if (v < 2560) {
            int w = v - 2048, row = w >> 3, c = w & 7;
            uint32_t off = (uint32_t)(row * 128 + c * 16);
            dst = st + STG_BH + (off ^ ((off >> 3) & 0x70));
            src = B + (size_t)row * KS + kb + c * 8;
        } else {
            int w = v - 2560, row = w >> 3, c = w & 7;
            uint32_t off = (uint32_t)(row * 128 + c * 16);
            dst = st + STG_BL + (off ^ ((off >> 3) & 0x70));
            src = B + (size_t)row * KS + 1024 + kb + c * 8;
        }
        cp16s(dst, src);
    }
}

// Issue the 12 MMAs of one chunk (4 x K16, 3 split terms). Caller = elect.
DI void issue_chunk(uint32_t tmem, uint32_t st, bool first) {
    uint64_t dAh = MK_DESC(st + STG_AH);
    uint64_t dAl = MK_DESC(st + STG_AL);
    uint64_t dBh = MK_DESC(st + STG_BH);
    uint64_t dBl = MK_DESC(st + STG_BL);
#pragma unroll
    for (int k = 0; k < 4; k++) {
        mma_f16_ss(tmem, dAh + 2 * k, dBh + 2 * k, (first && k == 0) ? 0u : 1u);
        mma_f16_ss(tmem, dAh + 2 * k, dBl + 2 * k, 1u);
        mma_f16_ss(tmem, dAl + 2 * k, dBh + 2 * k, 1u);
    }
}

// One GEMM phase: nch chunks (chunks 0..15 from A0/B0, 16..31 from A1/B1),
// result -> dd[64] (fp32 bits) per thread (row=tid), running chunk counter.
DI void do_phase(int nch,
                 const __nv_bfloat16* A0, const __nv_bfloat16* B0,
                 const __nv_bfloat16* A1, const __nv_bfloat16* B1,
                 uint32_t sbase, uint32_t tmem, uint32_t mb0, uint32_t mb1,
                 int& ctr, uint32_t* dd, int tid, int wid) {
#pragma unroll
    for (int i = 0; i < 2; i++) {
        int g = ctr + i;
        load_chunk(sbase + (g % 3) * STG_SZ, A0, B0, i, tid);
        cp_commit();
    }
    for (int i = 0; i < nch; i++) {
        int g = ctr + i;
        cp_wait1();
        __syncthreads();
        if (wid == 0) {
            if (elect1()) {
                asm volatile("fence.proxy.async.shared::cta;" ::: "memory");
                issue_chunk(tmem, sbase + (g % 3) * STG_SZ, i == 0);
                T5_COMMIT((g & 1) ? mb1 : mb0);
            }
        }
        if (g >= 1) {
            int gw = g - 1;
            MBAR_WAIT((gw & 1) ? mb1 : mb0, (uint32_t)((gw >> 1) & 1));
        }
        if (i + 2 < nch) {
            int j = i + 2, gg = g + 2;
            load_chunk(sbase + (gg % 3) * STG_SZ,
                       (j >= 16) ? A1 : A0, (j >= 16) ? B1 : B0, j & 15, tid);
        }
        cp_commit();
    }
    int gl = ctr + nch - 1;
    MBAR_WAIT((gl & 1) ? mb1 : mb0, (uint32_t)((gl >> 1) & 1));
    T5_FENCE_AFTER();
    T5_LD_X32(dd, tmem);
    T5_LD_X32(dd + 32, tmem + 32);
    T5_WAIT_LD();
    T5_FENCE_BEFORE();
    ctr += nch;
}
#endif  // T5_OK

// ----------------------- persistent scan (1 kernel) -------------------------
// 64 CTAs x 128 threads. CTA bid: N-tile n0=bid*64 ([i|f|g|o]x16 h-cols,
// h-cols j0=bid*16), M=128 = full batch.
__global__ void __launch_bounds__(128) k_scan(float* __restrict__ out) {
    extern __shared__ char dyn[];
    const int tid = threadIdx.x, wid = tid >> 5;
    const int n0 = blockIdx.x * 64, j0 = blockIdx.x * 16;

    float c0[16], c1[16];
#pragma unroll
    for (int i = 0; i < 16; i++) { c0[i] = 0.0f; c1[i] = 0.0f; }

#if T5_OK
    // ======================= tcgen05 implementation ========================
    __shared__ uint64_t s_mbar[2];
    __shared__ uint32_t s_tptr;

    uint32_t sbase = (smem_u32(dyn) + 1023u) & ~1023u;
    uint32_t mb0 = smem_u32(&s_mbar[0]), mb1 = smem_u32(&s_mbar[1]);

    if (wid == 0) T5_ALLOC(smem_u32(&s_tptr), 512);
    if (tid == 0) { MBAR_INIT(mb0, 1); MBAR_INIT(mb1, 1); }
    __syncthreads();
    uint32_t tmem;
    asm volatile("ld.shared.b32 %0, [%1];" : "=r"(tmem) : "r"(smem_u32(&s_tptr)));

    int ctr = 0;
    uint32_t dd[64];

    for (int t = 0; t < SEQ; t++) {
        const int p = t & 1;

        // ---- Phase A: gates0 = h0[p] @ Whh0'^T  (+gates_x in epilogue) ----
        do_phase(16, g_h0s[p], g_Whh0s + (size_t)n0 * KS,
                 g_h0s[p], g_Whh0s + (size_t)n0 * KS,
                 sbase, tmem, mb0, mb1, ctr, dd, tid, wid);
        {
            const float* gx = g_gates_x + ((size_t)(t * BATCH + tid)) * G4 + n0;
            __nv_bfloat16* hb = g_h0s[p ^ 1] + (size_t)tid * KS + j0;
#pragma unroll
            for (int jj = 0; jj < 16; jj++) {
                float iv = sigf (__uint_as_float(dd[jj])      + gx[jj]);
                float fv = sigf (__uint_as_float(dd[16 + jj]) + gx[16 + jj]);
                float gv = tanhf(__uint_as_float(dd[32 + jj]) + gx[32 + jj]);
                float ov = sigf (__uint_as_float(dd[48 + jj]) + gx[48 + jj]);
                float cn = fv * c0[jj] + iv * gv;
                c0[jj] = cn;
                float h = ov * tanhf(cn);
                __nv_bfloat16 hi = __float2bfloat16(h);
                hb[jj]        = hi;
                hb[1024 + jj] = __float2bfloat16(h - __bfloat162float(hi));
            }
        }
        grid_bar();

        // ---- Phase B: gates1 = h0[p^1]@Wih1'^T + h1[p]@Whh1'^T + bias1 ----
        do_phase(32, g_h0s[p ^ 1], g_Wih1s + (size_t)n0 * KS,
                 g_h1s[p], g_Whh1s + (size_t)n0 * KS,
                 sbase, tmem, mb0, mb1, ctr, dd, tid, wid);
        {
            const float* bs = g_bias1 + n0;
            __nv_bfloat16* hb = g_h1s[p ^ 1] + (size_t)tid * KS + j0;
            float* op = out + ((size_t)tid * SEQ + t) * HDIM + j0;
#pragma unroll
            for (int jj = 0; jj < 16; jj++) {
                float iv = sigf (__uint_as_float(dd[jj])      + bs[jj]);
                float fv = sigf (__uint_as_float(dd[16 + jj]) + bs[16 + jj]);
                float gv = tanhf(__uint_as_float(dd[32 + jj]) + bs[32 + jj]);
                float ov = sigf (__uint_as_float(dd[48 + jj]) + bs[48 + jj]);
                float cn = fv * c1[jj] + iv * gv;
                c1[jj] = cn;
                float h = ov * tanhf(cn);
                __nv_bfloat16 hi = __float2bfloat16(h);
                hb[jj]        = hi;
                hb[1024 + jj] = __float2bfloat16(h - __bfloat162float(hi));
                op[jj] = h;
            }
        }
        // no grid barrier here (parity double-buffering; see R9-R11 analysis)
    }

    __syncthreads();
    if (wid == 0) { T5_RELINQ(); T5_DEALLOC(tmem, 512); }

#else
    // =============== mma.sync fallback (non-'a' target pass) ===============
    // Same tile per CTA: M=128(batch) x N=64(gate tile). gemm_cp<128,64,2,2,128>
    // smem: sA 4*128*SSTR, sB 4*64*SSTR (110592B); sAcc (128x68 f32, 34816B)
    // unioned at base -- only overlaps stages 0-1, never stage 3 which the
    // final pipeline iteration reads; __syncthreads separates uses.
    __nv_bfloat16* sA = (__nv_bfloat16*)dyn;
    __nv_bfloat16* sB = sA + 4 * 128 * SSTR;
    float* sAcc = (float*)dyn;
    const int lane = tid & 31, warp = tid >> 5;
    const int wm = warp & 1, wn = warp >> 1;

    float acc[64];

    auto epi_to_smem = [&]() {
        __syncthreads();   // all warps done reading smem stages
#pragma unroll
        for (int mi = 0; mi < 4; mi++)
#pragma unroll
            for (int ng = 0; ng < 2; ng++)
#pragma unroll
                for (int hf = 0; hf < 2; hf++) {
                    const float* a4 = acc + ((mi * 4) + 2 * ng + hf) * 4;
                    int r = wm * 64 + mi * 16 + (lane >> 2);
                    int c = wn * 32 + ng * 16 + hf * 8 + ((lane & 3) << 1);
                    sAcc[r * 68 + c]           = a4[0];
                    sAcc[r * 68 + c + 1]       = a4[1];
                    sAcc[(r + 8) * 68 + c]     = a4[2];
                    sAcc[(r + 8) * 68 + c + 1] = a4[3];
                }
        __syncthreads();
    };

    for (int t = 0; t < SEQ; t++) {
        const int p = t & 1;

        // ---- Phase A ----
#pragma unroll
        for (int i = 0; i < 64; i++) acc[i] = 0.0f;
        gemm_cp<128, 64, 2, 2, 128>(g_h0s[p], g_Whh0s + (size_t)n0 * KS, acc, sA, sB);
        epi_to_smem();
        {
            const float* gx = g_gates_x + ((size_t)(t * BATCH + tid)) * G4 + n0;
            const float* ga = sAcc + tid * 68;
            __nv_bfloat16* hb = g_h0s[p ^ 1] + (size_t)tid * KS + j0;
#pragma unroll
            for (int jj = 0; jj < 16; jj++) {
                float iv = sigf (ga[jj]      + gx[jj]);
                float fv = sigf (ga[16 + jj] + gx[16 + jj]);
                float gv = tanhf(ga[32 + jj] + gx[32 + jj]);
                float ov = sigf (ga[48 + jj] + gx[48 + jj]);
                float cn = fv * c0[jj] + iv * gv;
                c0[jj] = cn;
                float h = ov * tanhf(cn);
                __nv_bfloat16 hi = __float2bfloat16(h);
                hb[jj]        = hi;
                hb[1024 + jj] = __float2bfloat16(h - __bfloat162float(hi));
            }
        }
        grid_bar();   // includes __syncthreads (orders sAcc reads vs reuse)

        // ---- Phase B ----
#pragma unroll
        for (int i = 0; i < 64; i++) acc[i] = 0.0f;
        gemm_cp<128, 64, 2, 2, 128>(g_h0s[p ^ 1], g_Wih1s + (size_t)n0 * KS, acc, sA, sB);
        gemm_cp<128, 64, 2, 2, 128>(g_h1s[p], g_Whh1s + (size_t)n0 * KS, acc, sA, sB);
        epi_to_smem();
        {
            const float* bs = g_bias1 + n0;
            const float* ga = sAcc + tid * 68;
            __nv_bfloat16* hb = g_h1s[p ^ 1] + (size_t)tid * KS + j0;
            float* op = out + ((size_t)tid * SEQ + t) * HDIM + j0;
#pragma unroll
            for (int jj = 0; jj < 16; jj++) {
                float iv = sigf (ga[jj]      + bs[jj]);
                float fv = sigf (ga[16 + jj] + bs[16 + jj]);
                float gv = tanhf(ga[32 + jj] + bs[32 + jj]);
                float ov = sigf (ga[48 + jj] + bs[48 + jj]);
                float cn = fv * c1[jj] + iv * gv;
                c1[jj] = cn;
                float h = ov * tanhf(cn);
                __nv_bfloat16 hi = __float2bfloat16(h);
                hb[jj]        = hi;
                hb[1024 + jj] = __float2bfloat16(h - __bfloat162float(hi));
                op[jj] = h;
            }
        }
        __syncthreads();   // sAcc reads done before next phase reuses smem
    }
#endif
}

// -------------------------------- launcher ----------------------------------
extern "C" void kernel_launch(void* const* d_in, const int* in_sizes, int n_in,
                              void* d_out, int out_size) {
    const float* x     = (const float*)d_in[0];
    const float* W_ih0 = (const float*)d_in[1];
    const float* b_ih0 = (const float*)d_in[2];
    const float* W_hh0 = (const float*)d_in[3];
    const float* b_hh0 = (const float*)d_in[4];
    const float* W_ih1 = (const float*)d_in[5];
    const float* b_ih1 = (const float*)d_in[6];
    const float* W_hh1 = (const float*)d_in[7];
    const float* b_hh1 = (const float*)d_in[8];
    float* out = (float*)d_out;

    cudaFuncSetAttribute(k_gemm_pre, cudaFuncAttributeMaxDynamicSharedMemorySize, PRE_SMEM);
    cudaFuncSetAttribute(k_scan,     cudaFuncAttributeMaxDynamicSharedMemorySize, SCAN_DYN);

    // prep
    k_split_w<<<(4 * G4 * FDIM + 255) / 256, 256>>>(W_ih0, W_hh0, W_ih1, W_hh1);
    k_bias<<<(G4 + 255) / 256, 256>>>(b_ih0, b_hh0, b_ih1, b_hh1);
    k_split_x<<<(MTOT * FDIM + 255) / 256, 256>>>(x);
    k_init<<<(BATCH * KS + 255) / 256, 256>>>();

    // input-projection GEMM for all timesteps
    k_gemm_pre<<<dim3(G4 / 128, MTOT / 128), 256, PRE_SMEM>>>();

    // persistent scan (tcgen05 on arch-specific cubin, mma.sync otherwise)
    k_scan<<<NCTA, 128, SCAN_DYN>>>(out);
}